// round 15
// baseline (speedup 1.0000x reference)
#include <cuda_runtime.h>
#include <cuda_fp16.h>

// FastFood layer, D=1024, R=4, M=16384 rows. PERSISTENT one-warp-per-row kernel.
// R14 structure: fp16 transpose image (CF 17-word rows), fp16 x-image cached per
// row, f32x2 register-pair butterflies, packed PG gather table.
// Persistence removes wave quantization (608 blocks, rows strided).
// Layouts: A: idx = k*32 + l   B: idx = l*32 + k  (k = reg-pair halves, l = lane)

#define FF_D 1024
#define FF_R 4
#define WPB 8
#define THREADS (WPB * 32)
#define RSH 34      // halves per transpose-image row
#define RSW 17      // words per transpose-image row
#define XOFF 544    // x-image word base (= 32*17)
#define IMGW 1056   // total words per warp (544 + 512)
#define GRID_BLOCKS 608   // 152 SMs x 4 resident blocks

typedef unsigned long long u64;
typedef unsigned int u32;

__device__ u32  g_bpack[FF_R * 32];   // bit k = signbit(B[r][k*32+l])
__device__ int4 g_pg4[FF_R * 256];    // [r][q*32+l]: entries for j = l*32+4q+{0..3}
__device__ int4 g_sh4[FF_R * 128];    // [r][q*32+l]: S'-half2 pairs p=4q..4q+3 at lane l

__global__ void prep_kernel(const float* __restrict__ B, const float* __restrict__ G,
                            const float* __restrict__ S, const int* __restrict__ P) {
    int t = blockIdx.x * blockDim.x + threadIdx.x;
    int stride = gridDim.x * blockDim.x;
    if (t < FF_R * 32) {
        int r = t >> 5, l = t & 31;
        u32 m = 0;
        #pragma unroll
        for (int k = 0; k < 32; k++)
            m |= (__float_as_uint(B[r * FF_D + k * 32 + l]) >> 31) << k;
        g_bpack[t] = m;
    }
    for (int i = t; i < FF_R * 256; i += stride) {
        int r = i >> 8, rem = i & 255;
        int q = rem >> 5, l = rem & 31;
        int j = r * FF_D + l * 32 + 4 * q;
        u32 e[4];
        #pragma unroll
        for (int u = 0; u < 4; u++) {
            int p = P[j + u];
            u32 slot = (u32)((p >> 5) * RSH + (p & 31));   // half-slot
            unsigned short gh = __half_as_ushort(__float2half_rn(G[j + u]));
            e[u] = (slot << 16) | (u32)gh;
        }
        g_pg4[i] = make_int4((int)e[0], (int)e[1], (int)e[2], (int)e[3]);
    }
    // S-half2 pairs, int4-grouped: component c of [r][q*32+l] = pair p = 4q+c.
    for (int i = t; i < FF_R * 128; i += stride) {
        int r = i >> 7, rem = i & 127;
        int q = rem >> 5, l = rem & 31;
        u32 e[4];
        #pragma unroll
        for (int c = 0; c < 4; c++) {
            int p = 4 * q + c;
            float s0 = S[r * FF_D + (2 * p)     * 32 + l] * 0.03125f;
            float s1 = S[r * FF_D + (2 * p + 1) * 32 + l] * 0.03125f;
            __half2 h = __floats2half2_rn(s0, s1);
            e[c] = *reinterpret_cast<u32*>(&h);
        }
        g_sh4[i] = make_int4((int)e[0], (int)e[1], (int)e[2], (int)e[3]);
    }
}

// ---- f32x2 helpers ----
__device__ __forceinline__ u64 pk(float a, float b) {
    u64 u; asm("mov.b64 %0, {%1,%2};" : "=l"(u) : "f"(a), "f"(b)); return u;
}
__device__ __forceinline__ float2 up(u64 u) {
    float2 r; asm("mov.b64 {%0,%1}, %2;" : "=f"(r.x), "=f"(r.y) : "l"(u)); return r;
}
__device__ __forceinline__ u64 swp(u64 v) {
    u64 r;
    asm("{\n\t.reg .b32 a,b;\n\tmov.b64 {a,b}, %1;\n\tmov.b64 %0, {b,a};\n\t}"
        : "=l"(r) : "l"(v));
    return r;
}
__device__ __forceinline__ u64 addx2(u64 a, u64 b) {
    u64 r; asm("add.rn.f32x2 %0, %1, %2;" : "=l"(r) : "l"(a), "l"(b)); return r;
}
__device__ __forceinline__ u64 fmax2(u64 a, u64 b, u64 c) {   // a*b + c
    u64 r; asm("fma.rn.f32x2 %0, %1, %2, %3;" : "=l"(r) : "l"(a), "l"(b), "l"(c)); return r;
}
__device__ __forceinline__ u64 mulx2(u64 a, u64 b) {
    u64 r; asm("mul.rn.f32x2 %0, %1, %2;" : "=l"(r) : "l"(a), "l"(b)); return r;
}
#define C_P1M1 0xBF8000003F800000ULL   // {+1.0, -1.0}
#define C_M1M1 0xBF800000BF800000ULL   // {-1.0, -1.0}

__device__ __forceinline__ u32 h2pack(u64 v) {
    float2 f = up(v);
    __half2 h = __floats2half2_rn(f.x, f.y);
    return *reinterpret_cast<u32*>(&h);
}
__device__ __forceinline__ float2 h2unpack(u32 w) {
    __half2 h = *reinterpret_cast<__half2*>(&w);
    return __half22float2(h);
}

// H32 over {half-bit of each pair} + {4 register-pair index bits}
__device__ __forceinline__ void fwht2x(u64 va[16]) {
    #pragma unroll
    for (int p = 0; p < 16; p++)
        va[p] = fmax2(va[p], C_P1M1, swp(va[p]));
    #pragma unroll
    for (int m = 1; m <= 8; m <<= 1) {
        #pragma unroll
        for (int p = 0; p < 16; p++) {
            if ((p & m) == 0) {
                u64 a = va[p], b = va[p | m];
                va[p]     = addx2(a, b);
                va[p | m] = fmax2(b, C_M1M1, a);
            }
        }
    }
}

__global__ __launch_bounds__(THREADS, 4)
void fastfood_kernel(const float* __restrict__ x,
                     float* __restrict__ out, int M)
{
    __shared__ u32 sc[WPB][IMGW];                  // 4224 B per warp
    const int warp = threadIdx.x >> 5;
    const int t    = threadIdx.x & 31;             // lane
    u32*    sm32 = sc[warp];
    __half* smh  = reinterpret_cast<__half*>(sm32);
    u32*    ximg = sm32 + XOFF;

    const int rstride = gridDim.x * WPB;

    for (int row = blockIdx.x * WPB + warp; row < M; row += rstride) {
        const float* xr = x + (size_t)row * FF_D;

        // ---- load x once per row, pack k-pairs to fp16, store to private x-image ----
        // word (p, t) written and read ONLY by this thread: no syncs needed.
        // (previous row's image traffic on these words was also this thread's.)
        #pragma unroll
        for (int p = 0; p < 16; p++) {
            float lo = __ldg(&xr[(2 * p)     * 32 + t]);
            float hi = __ldg(&xr[(2 * p + 1) * 32 + t]);
            __half2 h = __floats2half2_rn(lo, hi);
            ximg[p * 32 + t] = *reinterpret_cast<u32*>(&h);
        }

        #pragma unroll 1
        for (int r = 0; r < FF_R; r++) {
            // ---- v = x * B[r] (sign-bit xor on fp16-cached x), layout A ----
            const u32 bp = g_bpack[r * 32 + t];
            u64 va[16];
            #pragma unroll
            for (int p = 0; p < 16; p++) {
                float2 f = h2unpack(ximg[p * 32 + t]);
                u32 m0 = (bp << (31 - 2 * p))     & 0x80000000u;
                u32 m1 = (bp << (31 - 2 * p - 1)) & 0x80000000u;
                va[p] = pk(__uint_as_float(__float_as_uint(f.x) ^ m0),
                           __uint_as_float(__float_as_uint(f.y) ^ m1));
            }

            // ---- FWHT #1: high bits (layout A) ----
            fwht2x(va);
            // T1 write: value (k, t) -> row k, half t. CF (pair-merge).
            // (prev r/row T2 reads used this thread's identical columns: no sync)
            #pragma unroll
            for (int p = 0; p < 16; p++) {
                float2 f = up(va[p]);
                smh[(2 * p)     * RSH + t] = __float2half_rn(f.x);
                smh[(2 * p + 1) * RSH + t] = __float2half_rn(f.y);
            }
            __syncwarp();
            // T1 read: own row t, words w -> halves (k'=2w, 2w+1). CF (17 odd).
            #pragma unroll
            for (int w = 0; w < 16; w++) {
                float2 f = h2unpack(sm32[t * RSW + w]);
                va[w] = pk(f.x, f.y);
            }
            // ---- FWHT #1: low bits (layout B) -> h1 ----
            fwht2x(va);

            // ---- gather image: own-row word writes (only this thread read row t) ----
            #pragma unroll
            for (int w = 0; w < 16; w++)
                sm32[t * RSW + w] = h2pack(va[w]);
            __syncwarp();
            // ---- permuted gather * G: thread t <- j = t*32 + 4q + u ----
            const int4* PG = g_pg4 + r * 256;
            #pragma unroll
            for (int q = 0; q < 8; q++) {
                int4 pg = __ldg(&PG[q * 32 + t]);
                u32 e0 = (u32)pg.x, e1 = (u32)pg.y, e2 = (u32)pg.z, e3 = (u32)pg.w;
                float t0 = __half2float(smh[e0 >> 16]);
                float t1 = __half2float(smh[e1 >> 16]);
                float t2 = __half2float(smh[e2 >> 16]);
                float t3 = __half2float(smh[e3 >> 16]);
                float g0 = __half2float(__ushort_as_half((unsigned short)(e0 & 0xffffu)));
                float g1 = __half2float(__ushort_as_half((unsigned short)(e1 & 0xffffu)));
                float g2 = __half2float(__ushort_as_half((unsigned short)(e2 & 0xffffu)));
                float g3 = __half2float(__ushort_as_half((unsigned short)(e3 & 0xffffu)));
                va[2 * q]     = mulx2(pk(t0, t1), pk(g0, g1));
                va[2 * q + 1] = mulx2(pk(t2, t3), pk(g2, g3));
            }
            __syncwarp();                                   // gathers done before overwrite

            // ---- FWHT #2: low bits (layout B) ----
            fwht2x(va);
            // T2 write: own-row word writes. CF.
            #pragma unroll
            for (int w = 0; w < 16; w++)
                sm32[t * RSW + w] = h2pack(va[w]);
            __syncwarp();
            // T2 read: column side, value j = k*32 + t from row k half t. CF (pair-merge).
            #pragma unroll
            for (int p = 0; p < 16; p++) {
                float f0 = __half2float(smh[(2 * p)     * RSH + t]);
                float f1 = __half2float(smh[(2 * p + 1) * RSH + t]);
                va[p] = pk(f0, f1);
            }
            // ---- FWHT #2: high bits (layout A) ----
            fwht2x(va);

            // ---- scale (int4-grouped half2 S pairs) + coalesced store ----
            const int4* Sh = g_sh4 + r * 128;
            float* o = out + (size_t)row * (FF_R * FF_D) + r * FF_D;
            #pragma unroll
            for (int q = 0; q < 4; q++) {
                int4 sv = __ldg(&Sh[q * 32 + t]);
                u32 se[4] = {(u32)sv.x, (u32)sv.y, (u32)sv.z, (u32)sv.w};
                #pragma unroll
                for (int c = 0; c < 4; c++) {
                    int p = 4 * q + c;
                    float2 s = h2unpack(se[c]);
                    float2 f = up(mulx2(va[p], pk(s.x, s.y)));
                    o[(2 * p)     * 32 + t] = f.x;
                    o[(2 * p + 1) * 32 + t] = f.y;
                }
            }
        }
    }
}

extern "C" void kernel_launch(void* const* d_in, const int* in_sizes, int n_in,
                              void* d_out, int out_size) {
    const float* x = (const float*)d_in[0];   // (4,512,8,1024) fp32
    const float* B = (const float*)d_in[1];   // (4,1024) fp32
    const float* G = (const float*)d_in[2];   // (4,1024) fp32
    const float* S = (const float*)d_in[3];   // (4,1024) fp32
    const int*   P = (const int*)  d_in[4];   // (4,1024) int32
    float* out = (float*)d_out;

    const int M = in_sizes[0] / FF_D;         // 16384 rows
    prep_kernel<<<32, 256>>>(B, G, S, P);
    int blocks = (M + WPB - 1) / WPB;
    if (blocks > GRID_BLOCKS) blocks = GRID_BLOCKS;
    fastfood_kernel<<<blocks, THREADS>>>(x, out, M);
}

// round 16
// speedup vs baseline: 1.0315x; 1.0315x over previous
#include <cuda_runtime.h>
#include <cuda_fp16.h>

// FastFood layer, D=1024, R=4, M=16384 rows. One warp per row. Zero shuffles.
// R14 structure: fp16 transpose image (CF 17-word rows), fp16 x-image cached per
// row, f32x2 register-pair butterflies, packed PG gather table. Flat 2048-block
// launch (persistence regressed in R15).
// New: B applied as precomputed XOR masks on packed half2 words (sign bits 15/31),
// and S table int4-grouped. Both numerically exact vs R14.
// Layouts: A: idx = k*32 + l   B: idx = l*32 + k  (k = reg-pair halves, l = lane)

#define FF_D 1024
#define FF_R 4
#define WPB 8
#define THREADS (WPB * 32)
#define RSH 34      // halves per transpose-image row
#define RSW 17      // words per transpose-image row
#define XOFF 544    // x-image word base (= 32*17)
#define IMGW 1056   // total words per warp (544 + 512)

typedef unsigned long long u64;
typedef unsigned int u32;

__device__ int4 g_bm4[FF_R * 128];    // [r][q*32+t], comp c: half2 sign mask for pair p=4q+c
__device__ int4 g_pg4[FF_R * 256];    // [r][q*32+l]: entries for j = l*32+4q+{0..3}
__device__ int4 g_sh4[FF_R * 128];    // [r][q*32+l]: S'-half2 pairs p=4q..4q+3 at lane l

__global__ void prep_kernel(const float* __restrict__ B, const float* __restrict__ G,
                            const float* __restrict__ S, const int* __restrict__ P) {
    int t = blockIdx.x * blockDim.x + threadIdx.x;
    int stride = gridDim.x * blockDim.x;
    // B sign masks on packed half2 words: pair p holds (k=2p low half, k=2p+1 high half).
    for (int i = t; i < FF_R * 128; i += stride) {
        int r = i >> 7, rem = i & 127;
        int q = rem >> 5, l = rem & 31;
        u32 e[4];
        #pragma unroll
        for (int c = 0; c < 4; c++) {
            int p = 4 * q + c;
            u32 s0 = __float_as_uint(B[r * FF_D + (2 * p)     * 32 + l]) >> 31;
            u32 s1 = __float_as_uint(B[r * FF_D + (2 * p + 1) * 32 + l]) >> 31;
            e[c] = (s0 << 15) | (s1 << 31);
        }
        g_bm4[i] = make_int4((int)e[0], (int)e[1], (int)e[2], (int)e[3]);
    }
    for (int i = t; i < FF_R * 256; i += stride) {
        int r = i >> 8, rem = i & 255;
        int q = rem >> 5, l = rem & 31;
        int j = r * FF_D + l * 32 + 4 * q;
        u32 e[4];
        #pragma unroll
        for (int u = 0; u < 4; u++) {
            int p = P[j + u];
            u32 slot = (u32)((p >> 5) * RSH + (p & 31));   // half-slot
            unsigned short gh = __half_as_ushort(__float2half_rn(G[j + u]));
            e[u] = (slot << 16) | (u32)gh;
        }
        g_pg4[i] = make_int4((int)e[0], (int)e[1], (int)e[2], (int)e[3]);
    }
    // S-half2 pairs, int4-grouped: component c of [r][q*32+l] = pair p = 4q+c.
    for (int i = t; i < FF_R * 128; i += stride) {
        int r = i >> 7, rem = i & 127;
        int q = rem >> 5, l = rem & 31;
        u32 e[4];
        #pragma unroll
        for (int c = 0; c < 4; c++) {
            int p = 4 * q + c;
            float s0 = S[r * FF_D + (2 * p)     * 32 + l] * 0.03125f;
            float s1 = S[r * FF_D + (2 * p + 1) * 32 + l] * 0.03125f;
            __half2 h = __floats2half2_rn(s0, s1);
            e[c] = *reinterpret_cast<u32*>(&h);
        }
        g_sh4[i] = make_int4((int)e[0], (int)e[1], (int)e[2], (int)e[3]);
    }
}

// ---- f32x2 helpers ----
__device__ __forceinline__ u64 pk(float a, float b) {
    u64 u; asm("mov.b64 %0, {%1,%2};" : "=l"(u) : "f"(a), "f"(b)); return u;
}
__device__ __forceinline__ float2 up(u64 u) {
    float2 r; asm("mov.b64 {%0,%1}, %2;" : "=f"(r.x), "=f"(r.y) : "l"(u)); return r;
}
__device__ __forceinline__ u64 swp(u64 v) {
    u64 r;
    asm("{\n\t.reg .b32 a,b;\n\tmov.b64 {a,b}, %1;\n\tmov.b64 %0, {b,a};\n\t}"
        : "=l"(r) : "l"(v));
    return r;
}
__device__ __forceinline__ u64 addx2(u64 a, u64 b) {
    u64 r; asm("add.rn.f32x2 %0, %1, %2;" : "=l"(r) : "l"(a), "l"(b)); return r;
}
__device__ __forceinline__ u64 fmax2(u64 a, u64 b, u64 c) {   // a*b + c
    u64 r; asm("fma.rn.f32x2 %0, %1, %2, %3;" : "=l"(r) : "l"(a), "l"(b), "l"(c)); return r;
}
__device__ __forceinline__ u64 mulx2(u64 a, u64 b) {
    u64 r; asm("mul.rn.f32x2 %0, %1, %2;" : "=l"(r) : "l"(a), "l"(b)); return r;
}
#define C_P1M1 0xBF8000003F800000ULL   // {+1.0, -1.0}
#define C_M1M1 0xBF800000BF800000ULL   // {-1.0, -1.0}

__device__ __forceinline__ u32 h2pack(u64 v) {
    float2 f = up(v);
    __half2 h = __floats2half2_rn(f.x, f.y);
    return *reinterpret_cast<u32*>(&h);
}
__device__ __forceinline__ float2 h2unpack(u32 w) {
    __half2 h = *reinterpret_cast<__half2*>(&w);
    return __half22float2(h);
}

// H32 over {half-bit of each pair} + {4 register-pair index bits}
__device__ __forceinline__ void fwht2x(u64 va[16]) {
    #pragma unroll
    for (int p = 0; p < 16; p++)
        va[p] = fmax2(va[p], C_P1M1, swp(va[p]));
    #pragma unroll
    for (int m = 1; m <= 8; m <<= 1) {
        #pragma unroll
        for (int p = 0; p < 16; p++) {
            if ((p & m) == 0) {
                u64 a = va[p], b = va[p | m];
                va[p]     = addx2(a, b);
                va[p | m] = fmax2(b, C_M1M1, a);
            }
        }
    }
}

__global__ __launch_bounds__(THREADS, 4)
void fastfood_kernel(const float* __restrict__ x,
                     float* __restrict__ out, int M)
{
    __shared__ u32 sc[WPB][IMGW];                  // 4224 B per warp
    const int warp = threadIdx.x >> 5;
    const int t    = threadIdx.x & 31;             // lane
    const int row  = blockIdx.x * WPB + warp;
    if (row >= M) return;
    u32*    sm32 = sc[warp];
    __half* smh  = reinterpret_cast<__half*>(sm32);
    u32*    ximg = sm32 + XOFF;
    const float* xr = x + (size_t)row * FF_D;

    // ---- load x once, pack k-pairs to fp16, store to private x-image ----
    // word (p, t) written and later read ONLY by this thread: no syncs needed.
    #pragma unroll
    for (int p = 0; p < 16; p++) {
        float lo = __ldg(&xr[(2 * p)     * 32 + t]);
        float hi = __ldg(&xr[(2 * p + 1) * 32 + t]);
        __half2 h = __floats2half2_rn(lo, hi);
        ximg[p * 32 + t] = *reinterpret_cast<u32*>(&h);
    }

    #pragma unroll 1
    for (int r = 0; r < FF_R; r++) {
        // ---- v = x * B[r]: XOR precomputed sign masks on packed half2 words ----
        const int4* BM = g_bm4 + r * 128;
        u64 va[16];
        #pragma unroll
        for (int q = 0; q < 4; q++) {
            int4 bm = __ldg(&BM[q * 32 + t]);
            u32 me[4] = {(u32)bm.x, (u32)bm.y, (u32)bm.z, (u32)bm.w};
            #pragma unroll
            for (int c = 0; c < 4; c++) {
                int p = 4 * q + c;
                float2 f = h2unpack(ximg[p * 32 + t] ^ me[c]);
                va[p] = pk(f.x, f.y);
            }
        }

        // ---- FWHT #1: high bits (layout A) ----
        fwht2x(va);
        // T1 write: value (k, t) -> row k, half t. CF (pair-merge).
        // (prev iter's T2 reads used this thread's identical columns: no sync)
        #pragma unroll
        for (int p = 0; p < 16; p++) {
            float2 f = up(va[p]);
            smh[(2 * p)     * RSH + t] = __float2half_rn(f.x);
            smh[(2 * p + 1) * RSH + t] = __float2half_rn(f.y);
        }
        __syncwarp();
        // T1 read: own row t, words w -> halves (k'=2w, 2w+1). CF (17 odd).
        #pragma unroll
        for (int w = 0; w < 16; w++) {
            float2 f = h2unpack(sm32[t * RSW + w]);
            va[w] = pk(f.x, f.y);
        }
        // ---- FWHT #1: low bits (layout B) -> h1 ----
        fwht2x(va);

        // ---- gather image: own-row word writes (only this thread read row t) ----
        #pragma unroll
        for (int w = 0; w < 16; w++)
            sm32[t * RSW + w] = h2pack(va[w]);
        __syncwarp();
        // ---- permuted gather * G: thread t <- j = t*32 + 4q + u ----
        const int4* PG = g_pg4 + r * 256;
        #pragma unroll
        for (int q = 0; q < 8; q++) {
            int4 pg = __ldg(&PG[q * 32 + t]);
            u32 e0 = (u32)pg.x, e1 = (u32)pg.y, e2 = (u32)pg.z, e3 = (u32)pg.w;
            float t0 = __half2float(smh[e0 >> 16]);
            float t1 = __half2float(smh[e1 >> 16]);
            float t2 = __half2float(smh[e2 >> 16]);
            float t3 = __half2float(smh[e3 >> 16]);
            float g0 = __half2float(__ushort_as_half((unsigned short)(e0 & 0xffffu)));
            float g1 = __half2float(__ushort_as_half((unsigned short)(e1 & 0xffffu)));
            float g2 = __half2float(__ushort_as_half((unsigned short)(e2 & 0xffffu)));
            float g3 = __half2float(__ushort_as_half((unsigned short)(e3 & 0xffffu)));
            va[2 * q]     = mulx2(pk(t0, t1), pk(g0, g1));
            va[2 * q + 1] = mulx2(pk(t2, t3), pk(g2, g3));
        }
        __syncwarp();                                   // all gathers done before overwrite

        // ---- FWHT #2: low bits (layout B) ----
        fwht2x(va);
        // T2 write: own-row word writes. CF.
        #pragma unroll
        for (int w = 0; w < 16; w++)
            sm32[t * RSW + w] = h2pack(va[w]);
        __syncwarp();
        // T2 read: column side, value j = k*32 + t from row k half t. CF (pair-merge).
        #pragma unroll
        for (int p = 0; p < 16; p++) {
            float f0 = __half2float(smh[(2 * p)     * RSH + t]);
            float f1 = __half2float(smh[(2 * p + 1) * RSH + t]);
            va[p] = pk(f0, f1);
        }
        // ---- FWHT #2: high bits (layout A) ----
        fwht2x(va);

        // ---- scale (int4-grouped half2 S pairs) + coalesced store ----
        const int4* Sh = g_sh4 + r * 128;
        float* o = out + (size_t)row * (FF_R * FF_D) + r * FF_D;
        #pragma unroll
        for (int q = 0; q < 4; q++) {
            int4 sv = __ldg(&Sh[q * 32 + t]);
            u32 se[4] = {(u32)sv.x, (u32)sv.y, (u32)sv.z, (u32)sv.w};
            #pragma unroll
            for (int c = 0; c < 4; c++) {
                int p = 4 * q + c;
                float2 s = h2unpack(se[c]);
                float2 f = up(mulx2(va[p], pk(s.x, s.y)));
                o[(2 * p)     * 32 + t] = f.x;
                o[(2 * p + 1) * 32 + t] = f.y;
            }
        }
    }
}

extern "C" void kernel_launch(void* const* d_in, const int* in_sizes, int n_in,
                              void* d_out, int out_size) {
    const float* x = (const float*)d_in[0];   // (4,512,8,1024) fp32
    const float* B = (const float*)d_in[1];   // (4,1024) fp32
    const float* G = (const float*)d_in[2];   // (4,1024) fp32
    const float* S = (const float*)d_in[3];   // (4,1024) fp32
    const int*   P = (const int*)  d_in[4];   // (4,1024) int32
    float* out = (float*)d_out;

    const int M = in_sizes[0] / FF_D;         // 16384 rows
    prep_kernel<<<32, 256>>>(B, G, S, P);
    const int blocks = (M + WPB - 1) / WPB;
    fastfood_kernel<<<blocks, THREADS>>>(x, out, M);
}

// round 17
// speedup vs baseline: 1.1045x; 1.0708x over previous
#include <cuda_runtime.h>
#include <cuda_fp16.h>

// FastFood layer, D=1024, R=4, M=16384 rows. One warp per row. Zero shuffles.
// R14 structure: fp16 transpose image (CF 17-word rows), fp16 x-image, f32x2
// register-pair butterflies, packed PG gather table, flat 2048-block launch.
// R17 delta: r=0 consumes x directly from the fp32 global loads (sign applied in
// fp32) while the fp16 x-image is written for r=1..3 — removes one image read
// and the serial load->store->load head of each row.
// Layouts: A: idx = k*32 + l   B: idx = l*32 + k  (k = reg-pair halves, l = lane)

#define FF_D 1024
#define FF_R 4
#define WPB 8
#define THREADS (WPB * 32)
#define RSH 34      // halves per transpose-image row
#define RSW 17      // words per transpose-image row
#define XOFF 544    // x-image word base (= 32*17)
#define IMGW 1056   // total words per warp (544 + 512)

typedef unsigned long long u64;
typedef unsigned int u32;

__device__ u32  g_bpack[FF_R * 32];   // bit k = signbit(B[r][k*32+l])
__device__ int4 g_pg4[FF_R * 256];    // [r][q*32+l]: entries for j = l*32+4q+{0..3}
__device__ u32  g_sh2[FF_R * 512];    // [r][p*32+l] = half2(S'[2p*32+l], S'[(2p+1)*32+l])

__global__ void prep_kernel(const float* __restrict__ B, const float* __restrict__ G,
                            const float* __restrict__ S, const int* __restrict__ P) {
    int t = blockIdx.x * blockDim.x + threadIdx.x;
    int stride = gridDim.x * blockDim.x;
    if (t < FF_R * 32) {
        int r = t >> 5, l = t & 31;
        u32 m = 0;
        #pragma unroll
        for (int k = 0; k < 32; k++)
            m |= (__float_as_uint(B[r * FF_D + k * 32 + l]) >> 31) << k;
        g_bpack[t] = m;
    }
    for (int i = t; i < FF_R * 256; i += stride) {
        int r = i >> 8, rem = i & 255;
        int q = rem >> 5, l = rem & 31;
        int j = r * FF_D + l * 32 + 4 * q;
        u32 e[4];
        #pragma unroll
        for (int u = 0; u < 4; u++) {
            int p = P[j + u];
            u32 slot = (u32)((p >> 5) * RSH + (p & 31));   // half-slot
            unsigned short gh = __half_as_ushort(__float2half_rn(G[j + u]));
            e[u] = (slot << 16) | (u32)gh;
        }
        g_pg4[i] = make_int4((int)e[0], (int)e[1], (int)e[2], (int)e[3]);
    }
    for (int i = t; i < FF_R * 512; i += stride) {
        int r = i >> 9, rem = i & 511;
        int p = rem >> 5, l = rem & 31;
        float s0 = S[r * FF_D + (2 * p)     * 32 + l] * 0.03125f;
        float s1 = S[r * FF_D + (2 * p + 1) * 32 + l] * 0.03125f;
        __half2 h = __floats2half2_rn(s0, s1);
        g_sh2[i] = *reinterpret_cast<u32*>(&h);
    }
}

// ---- f32x2 helpers ----
__device__ __forceinline__ u64 pk(float a, float b) {
    u64 u; asm("mov.b64 %0, {%1,%2};" : "=l"(u) : "f"(a), "f"(b)); return u;
}
__device__ __forceinline__ float2 up(u64 u) {
    float2 r; asm("mov.b64 {%0,%1}, %2;" : "=f"(r.x), "=f"(r.y) : "l"(u)); return r;
}
__device__ __forceinline__ u64 swp(u64 v) {
    u64 r;
    asm("{\n\t.reg .b32 a,b;\n\tmov.b64 {a,b}, %1;\n\tmov.b64 %0, {b,a};\n\t}"
        : "=l"(r) : "l"(v));
    return r;
}
__device__ __forceinline__ u64 addx2(u64 a, u64 b) {
    u64 r; asm("add.rn.f32x2 %0, %1, %2;" : "=l"(r) : "l"(a), "l"(b)); return r;
}
__device__ __forceinline__ u64 fmax2(u64 a, u64 b, u64 c) {   // a*b + c
    u64 r; asm("fma.rn.f32x2 %0, %1, %2, %3;" : "=l"(r) : "l"(a), "l"(b), "l"(c)); return r;
}
__device__ __forceinline__ u64 mulx2(u64 a, u64 b) {
    u64 r; asm("mul.rn.f32x2 %0, %1, %2;" : "=l"(r) : "l"(a), "l"(b)); return r;
}
#define C_P1M1 0xBF8000003F800000ULL   // {+1.0, -1.0}
#define C_M1M1 0xBF800000BF800000ULL   // {-1.0, -1.0}

__device__ __forceinline__ u32 h2pack(u64 v) {
    float2 f = up(v);
    __half2 h = __floats2half2_rn(f.x, f.y);
    return *reinterpret_cast<u32*>(&h);
}
__device__ __forceinline__ float2 h2unpack(u32 w) {
    __half2 h = *reinterpret_cast<__half2*>(&w);
    return __half22float2(h);
}

// H32 over {half-bit of each pair} + {4 register-pair index bits}
__device__ __forceinline__ void fwht2x(u64 va[16]) {
    #pragma unroll
    for (int p = 0; p < 16; p++)
        va[p] = fmax2(va[p], C_P1M1, swp(va[p]));
    #pragma unroll
    for (int m = 1; m <= 8; m <<= 1) {
        #pragma unroll
        for (int p = 0; p < 16; p++) {
            if ((p & m) == 0) {
                u64 a = va[p], b = va[p | m];
                va[p]     = addx2(a, b);
                va[p | m] = fmax2(b, C_M1M1, a);
            }
        }
    }
}

// Common per-r tail: va holds x*B[r] in layout A; runs both FWHTs, the permuted
// gather*G, the S scale, and the coalesced store. Identical to R14's loop body.
__device__ __forceinline__ void process_r(u64 va[16], int r, u32* sm32, __half* smh,
                                          int t, float* o) {
    // ---- FWHT #1: high bits (layout A) ----
    fwht2x(va);
    // T1 write: value (k, t) -> row k, half t. CF (pair-merge).
    #pragma unroll
    for (int p = 0; p < 16; p++) {
        float2 f = up(va[p]);
        smh[(2 * p)     * RSH + t] = __float2half_rn(f.x);
        smh[(2 * p + 1) * RSH + t] = __float2half_rn(f.y);
    }
    __syncwarp();
    // T1 read: own row t, words w -> halves (k'=2w, 2w+1). CF (17 odd).
    #pragma unroll
    for (int w = 0; w < 16; w++) {
        float2 f = h2unpack(sm32[t * RSW + w]);
        va[w] = pk(f.x, f.y);
    }
    // ---- FWHT #1: low bits (layout B) -> h1 ----
    fwht2x(va);

    // ---- gather image: own-row word writes (only this thread read row t) ----
    #pragma unroll
    for (int w = 0; w < 16; w++)
        sm32[t * RSW + w] = h2pack(va[w]);
    __syncwarp();
    // ---- permuted gather * G: thread t <- j = t*32 + 4q + u ----
    const int4* PG = g_pg4 + r * 256;
    #pragma unroll
    for (int q = 0; q < 8; q++) {
        int4 pg = __ldg(&PG[q * 32 + t]);
        u32 e0 = (u32)pg.x, e1 = (u32)pg.y, e2 = (u32)pg.z, e3 = (u32)pg.w;
        float t0 = __half2float(smh[e0 >> 16]);
        float t1 = __half2float(smh[e1 >> 16]);
        float t2 = __half2float(smh[e2 >> 16]);
        float t3 = __half2float(smh[e3 >> 16]);
        float g0 = __half2float(__ushort_as_half((unsigned short)(e0 & 0xffffu)));
        float g1 = __half2float(__ushort_as_half((unsigned short)(e1 & 0xffffu)));
        float g2 = __half2float(__ushort_as_half((unsigned short)(e2 & 0xffffu)));
        float g3 = __half2float(__ushort_as_half((unsigned short)(e3 & 0xffffu)));
        va[2 * q]     = mulx2(pk(t0, t1), pk(g0, g1));
        va[2 * q + 1] = mulx2(pk(t2, t3), pk(g2, g3));
    }
    __syncwarp();                                   // all gathers done before overwrite

    // ---- FWHT #2: low bits (layout B) ----
    fwht2x(va);
    // T2 write: own-row word writes. CF.
    #pragma unroll
    for (int w = 0; w < 16; w++)
        sm32[t * RSW + w] = h2pack(va[w]);
    __syncwarp();
    // T2 read: column side, value j = k*32 + t from row k half t. CF (pair-merge).
    #pragma unroll
    for (int p = 0; p < 16; p++) {
        float f0 = __half2float(smh[(2 * p)     * RSH + t]);
        float f1 = __half2float(smh[(2 * p + 1) * RSH + t]);
        va[p] = pk(f0, f1);
    }
    // ---- FWHT #2: high bits (layout A) ----
    fwht2x(va);

    // ---- scale (half2-paired prescaled S) + coalesced store ----
    const u32* Sh = g_sh2 + r * 512;
    #pragma unroll
    for (int p = 0; p < 16; p++) {
        float2 s = h2unpack(__ldg(&Sh[p * 32 + t]));
        float2 f = up(mulx2(va[p], pk(s.x, s.y)));
        o[(2 * p)     * 32 + t] = f.x;
        o[(2 * p + 1) * 32 + t] = f.y;
    }
}

__global__ __launch_bounds__(THREADS, 4)
void fastfood_kernel(const float* __restrict__ x,
                     float* __restrict__ out, int M)
{
    __shared__ u32 sc[WPB][IMGW];                  // 4224 B per warp
    const int warp = threadIdx.x >> 5;
    const int t    = threadIdx.x & 31;             // lane
    const int row  = blockIdx.x * WPB + warp;
    if (row >= M) return;
    u32*    sm32 = sc[warp];
    __half* smh  = reinterpret_cast<__half*>(sm32);
    u32*    ximg = sm32 + XOFF;
    const float* xr = x + (size_t)row * FF_D;
    float* orow = out + (size_t)row * (FF_R * FF_D);

    // ---- r = 0: consume x directly from fp32 loads; write fp16 x-image for r>=1 ----
    // x-image word (p, t) written and later read ONLY by this thread: no syncs.
    {
        const u32 bp = g_bpack[t];                 // r = 0
        u64 va[16];
        #pragma unroll
        for (int p = 0; p < 16; p++) {
            float lo = __ldg(&xr[(2 * p)     * 32 + t]);
            float hi = __ldg(&xr[(2 * p + 1) * 32 + t]);
            __half2 h = __floats2half2_rn(lo, hi);
            ximg[p * 32 + t] = *reinterpret_cast<u32*>(&h);
            u32 m0 = (bp << (31 - 2 * p))     & 0x80000000u;
            u32 m1 = (bp << (31 - 2 * p - 1)) & 0x80000000u;
            va[p] = pk(__uint_as_float(__float_as_uint(lo) ^ m0),
                       __uint_as_float(__float_as_uint(hi) ^ m1));
        }
        process_r(va, 0, sm32, smh, t, orow);
    }

    // ---- r = 1..3: fp16-cached x ----
    #pragma unroll 1
    for (int r = 1; r < FF_R; r++) {
        const u32 bp = g_bpack[r * 32 + t];
        u64 va[16];
        #pragma unroll
        for (int p = 0; p < 16; p++) {
            float2 f = h2unpack(ximg[p * 32 + t]);
            u32 m0 = (bp << (31 - 2 * p))     & 0x80000000u;
            u32 m1 = (bp << (31 - 2 * p - 1)) & 0x80000000u;
            va[p] = pk(__uint_as_float(__float_as_uint(f.x) ^ m0),
                       __uint_as_float(__float_as_uint(f.y) ^ m1));
        }
        process_r(va, r, sm32, smh, t, orow + r * FF_D);
    }
}

extern "C" void kernel_launch(void* const* d_in, const int* in_sizes, int n_in,
                              void* d_out, int out_size) {
    const float* x = (const float*)d_in[0];   // (4,512,8,1024) fp32
    const float* B = (const float*)d_in[1];   // (4,1024) fp32
    const float* G = (const float*)d_in[2];   // (4,1024) fp32
    const float* S = (const float*)d_in[3];   // (4,1024) fp32
    const int*   P = (const int*)  d_in[4];   // (4,1024) int32
    float* out = (float*)d_out;

    const int M = in_sizes[0] / FF_D;         // 16384 rows
    prep_kernel<<<32, 256>>>(B, G, S, P);
    const int blocks = (M + WPB - 1) / WPB;
    fastfood_kernel<<<blocks, THREADS>>>(x, out, M);
}